// round 1
// baseline (speedup 1.0000x reference)
#include <cuda_runtime.h>

#define Bc 2
#define Sc 2048
#define Dc 1024
#define Hc 16
#define HDc 64
#define Mc (Bc*Sc)

// Scratch (static device globals; no runtime allocation)
__device__ float g_q[(size_t)Mc * Dc];
__device__ float g_k[(size_t)Mc * Dc];
__device__ float g_v[(size_t)Mc * Dc];
__device__ float g_ao[(size_t)Mc * Dc];
__device__ float g_m[Mc * Hc];
__device__ float g_l[Mc * Hc];

// C[m][n] = sum_k A[m][k] * Bm[n][k]   (A: MxK row-major, Bm: NxK row-major)
__global__ __launch_bounds__(256) void sgemm_nt(const float* __restrict__ A,
                                                const float* __restrict__ Bm,
                                                float* __restrict__ C,
                                                int M, int N, int K) {
    __shared__ float As[16][132];
    __shared__ float Bs[16][132];
    int t = threadIdx.x;
    int tx = t & 15, ty = t >> 4;
    int brow = blockIdx.y * 128, bcol = blockIdx.x * 128;
    float acc[8][8];
#pragma unroll
    for (int i = 0; i < 8; i++)
#pragma unroll
        for (int j = 0; j < 8; j++) acc[i][j] = 0.f;

    for (int k0 = 0; k0 < K; k0 += 16) {
#pragma unroll
        for (int l = 0; l < 2; l++) {
            int lin = t + l * 256;          // 0..511
            int r = lin >> 2;               // 0..127
            int c = (lin & 3) * 4;          // 0,4,8,12
            float4 va = *reinterpret_cast<const float4*>(A + (size_t)(brow + r) * K + k0 + c);
            As[c + 0][r] = va.x; As[c + 1][r] = va.y; As[c + 2][r] = va.z; As[c + 3][r] = va.w;
            float4 vb = *reinterpret_cast<const float4*>(Bm + (size_t)(bcol + r) * K + k0 + c);
            Bs[c + 0][r] = vb.x; Bs[c + 1][r] = vb.y; Bs[c + 2][r] = vb.z; Bs[c + 3][r] = vb.w;
        }
        __syncthreads();
#pragma unroll
        for (int kk = 0; kk < 16; kk++) {
            float4 a0 = *reinterpret_cast<float4*>(&As[kk][ty * 8]);
            float4 a1 = *reinterpret_cast<float4*>(&As[kk][ty * 8 + 4]);
            float4 b0 = *reinterpret_cast<float4*>(&Bs[kk][tx * 8]);
            float4 b1 = *reinterpret_cast<float4*>(&Bs[kk][tx * 8 + 4]);
            float a[8] = {a0.x, a0.y, a0.z, a0.w, a1.x, a1.y, a1.z, a1.w};
            float b[8] = {b0.x, b0.y, b0.z, b0.w, b1.x, b1.y, b1.z, b1.w};
#pragma unroll
            for (int i = 0; i < 8; i++)
#pragma unroll
                for (int j = 0; j < 8; j++)
                    acc[i][j] = fmaf(a[i], b[j], acc[i][j]);
        }
        __syncthreads();
    }
#pragma unroll
    for (int i = 0; i < 8; i++) {
        float* cp = C + (size_t)(brow + ty * 8 + i) * N + bcol + tx * 8;
        *reinterpret_cast<float4*>(cp)     = make_float4(acc[i][0], acc[i][1], acc[i][2], acc[i][3]);
        *reinterpret_cast<float4*>(cp + 4) = make_float4(acc[i][4], acc[i][5], acc[i][6], acc[i][7]);
    }
}

// In-place RoPE on g_q (blockIdx.y==0) / g_k (blockIdx.y==1)
__global__ __launch_bounds__(256) void rope_kernel(const float* __restrict__ cosb,
                                                   const float* __restrict__ sinb) {
    int tid = blockIdx.x * 256 + threadIdx.x;   // pair index
    int i = tid & 31;
    int h = (tid >> 5) & 15;
    int s = (tid >> 9) & 2047;
    int b = tid >> 20;
    float* p = blockIdx.y ? g_k : g_q;
    size_t off = ((size_t)(b * Sc + s)) * Dc + h * HDc + 2 * i;
    float2 t2 = *reinterpret_cast<float2*>(p + off);
    float c = cosb[s * 32 + i], sn = sinb[s * 32 + i];
    *reinterpret_cast<float2*>(p + off) = make_float2(t2.x * c - t2.y * sn,
                                                      t2.x * sn + t2.y * c);
}

// Pass 1: raw scaled scores -> attn buffer (scratch), online row max & sumexp -> g_m/g_l
__global__ __launch_bounds__(256) void attn_scores(float* __restrict__ attn) {
    __shared__ float Qs[64][68];   // [dd][i]
    __shared__ float Ks[64][68];   // [dd][j]
    int t = threadIdx.x;
    int tx = t & 15, ty = t >> 4;
    int bh = blockIdx.y;
    int b = bh >> 4, h = bh & 15;
    int i0 = blockIdx.x * 64;

    const float* qb = g_q + ((size_t)(b * Sc + i0)) * Dc + h * HDc;
#pragma unroll
    for (int l = 0; l < 4; l++) {
        int lin = t + l * 256;
        int r = lin >> 4;
        int c = (lin & 15) * 4;
        float4 v = *reinterpret_cast<const float4*>(qb + (size_t)r * Dc + c);
        Qs[c + 0][r] = v.x; Qs[c + 1][r] = v.y; Qs[c + 2][r] = v.z; Qs[c + 3][r] = v.w;
    }
    float m[4], l_[4];
#pragma unroll
    for (int r = 0; r < 4; r++) { m[r] = __int_as_float(0xff800000u); l_[r] = 0.f; }

    for (int jt = 0; jt < 32; jt++) {
        int j0 = jt * 64;
        const float* kb = g_k + ((size_t)(b * Sc + j0)) * Dc + h * HDc;
        __syncthreads();
#pragma unroll
        for (int l = 0; l < 4; l++) {
            int lin = t + l * 256;
            int r = lin >> 4;
            int c = (lin & 15) * 4;
            float4 v = *reinterpret_cast<const float4*>(kb + (size_t)r * Dc + c);
            Ks[c + 0][r] = v.x; Ks[c + 1][r] = v.y; Ks[c + 2][r] = v.z; Ks[c + 3][r] = v.w;
        }
        __syncthreads();

        float s[4][4];
#pragma unroll
        for (int i = 0; i < 4; i++)
#pragma unroll
            for (int j = 0; j < 4; j++) s[i][j] = 0.f;

#pragma unroll 16
        for (int kk = 0; kk < 64; kk++) {
            float4 av = *reinterpret_cast<float4*>(&Qs[kk][ty * 4]);
            float4 bv = *reinterpret_cast<float4*>(&Ks[kk][tx * 4]);
            float a[4] = {av.x, av.y, av.z, av.w};
            float bb[4] = {bv.x, bv.y, bv.z, bv.w};
#pragma unroll
            for (int i = 0; i < 4; i++)
#pragma unroll
                for (int j = 0; j < 4; j++)
                    s[i][j] = fmaf(a[i], bb[j], s[i][j]);
        }

#pragma unroll
        for (int r = 0; r < 4; r++) {
            s[r][0] *= 0.125f; s[r][1] *= 0.125f; s[r][2] *= 0.125f; s[r][3] *= 0.125f;
            float rmax = fmaxf(fmaxf(s[r][0], s[r][1]), fmaxf(s[r][2], s[r][3]));
#pragma unroll
            for (int o = 8; o > 0; o >>= 1)
                rmax = fmaxf(rmax, __shfl_xor_sync(0xffffffffu, rmax, o, 16));
            float mn = fmaxf(m[r], rmax);
            float corr = __expf(m[r] - mn);
            float ps = __expf(s[r][0] - mn) + __expf(s[r][1] - mn) +
                       __expf(s[r][2] - mn) + __expf(s[r][3] - mn);
#pragma unroll
            for (int o = 8; o > 0; o >>= 1)
                ps += __shfl_xor_sync(0xffffffffu, ps, o, 16);
            l_[r] = l_[r] * corr + ps;
            m[r] = mn;
            size_t off = ((size_t)((b * Sc + i0 + ty * 4 + r) * Hc + h)) * Sc + j0 + tx * 4;
            *reinterpret_cast<float4*>(attn + off) = make_float4(s[r][0], s[r][1], s[r][2], s[r][3]);
        }
    }
    if (tx == 0) {
#pragma unroll
        for (int r = 0; r < 4; r++) {
            int idx = (b * Sc + i0 + ty * 4 + r) * Hc + h;
            g_m[idx] = m[r];
            g_l[idx] = l_[r];
        }
    }
}

// Pass 2: normalize weights (final output), entropy, o = w @ V
__global__ __launch_bounds__(256) void attn_av(float* __restrict__ attn, float* __restrict__ ent) {
    __shared__ float Ws[64][68];   // [j][i]
    __shared__ float Vs[64][68];   // [j][c]
    int t = threadIdx.x;
    int tx = t & 15, ty = t >> 4;
    int bh = blockIdx.y;
    int b = bh >> 4, h = bh & 15;
    int i0 = blockIdx.x * 64;

    float m[4], linv[4], entacc[4] = {0.f, 0.f, 0.f, 0.f};
#pragma unroll
    for (int r = 0; r < 4; r++) {
        int idx = (b * Sc + i0 + ty * 4 + r) * Hc + h;
        m[r] = g_m[idx];
        linv[r] = 1.f / g_l[idx];
    }
    float o[4][4];
#pragma unroll
    for (int i = 0; i < 4; i++)
#pragma unroll
        for (int j = 0; j < 4; j++) o[i][j] = 0.f;

    for (int jt = 0; jt < 32; jt++) {
        int j0 = jt * 64;
        __syncthreads();
#pragma unroll
        for (int r = 0; r < 4; r++) {
            size_t off = ((size_t)((b * Sc + i0 + ty * 4 + r) * Hc + h)) * Sc + j0 + tx * 4;
            float4 sv = *reinterpret_cast<const float4*>(attn + off);
            float4 w;
            w.x = __expf(sv.x - m[r]) * linv[r];
            w.y = __expf(sv.y - m[r]) * linv[r];
            w.z = __expf(sv.z - m[r]) * linv[r];
            w.w = __expf(sv.w - m[r]) * linv[r];
            entacc[r] += w.x * __log2f(w.x + 1e-9f) + w.y * __log2f(w.y + 1e-9f) +
                         w.z * __log2f(w.z + 1e-9f) + w.w * __log2f(w.w + 1e-9f);
            *reinterpret_cast<float4*>(attn + off) = w;
            Ws[tx * 4 + 0][ty * 4 + r] = w.x;
            Ws[tx * 4 + 1][ty * 4 + r] = w.y;
            Ws[tx * 4 + 2][ty * 4 + r] = w.z;
            Ws[tx * 4 + 3][ty * 4 + r] = w.w;
        }
        const float* vb = g_v + ((size_t)(b * Sc + j0)) * Dc + h * HDc;
#pragma unroll
        for (int l = 0; l < 4; l++) {
            int lin = t + l * 256;
            int r = lin >> 4;
            int c = (lin & 15) * 4;
            *reinterpret_cast<float4*>(&Vs[r][c]) =
                *reinterpret_cast<const float4*>(vb + (size_t)r * Dc + c);
        }
        __syncthreads();
#pragma unroll 16
        for (int jj = 0; jj < 64; jj++) {
            float4 av = *reinterpret_cast<float4*>(&Ws[jj][ty * 4]);
            float4 bv = *reinterpret_cast<float4*>(&Vs[jj][tx * 4]);
            float a[4] = {av.x, av.y, av.z, av.w};
            float bb[4] = {bv.x, bv.y, bv.z, bv.w};
#pragma unroll
            for (int i = 0; i < 4; i++)
#pragma unroll
                for (int j = 0; j < 4; j++)
                    o[i][j] = fmaf(a[i], bb[j], o[i][j]);
        }
    }
#pragma unroll
    for (int r = 0; r < 4; r++) {
        float* op = g_ao + ((size_t)(b * Sc + i0 + ty * 4 + r)) * Dc + h * HDc + tx * 4;
        *reinterpret_cast<float4*>(op) = make_float4(o[r][0], o[r][1], o[r][2], o[r][3]);
    }
#pragma unroll
    for (int r = 0; r < 4; r++) {
        float e = entacc[r];
#pragma unroll
        for (int oo = 8; oo > 0; oo >>= 1)
            e += __shfl_xor_sync(0xffffffffu, e, oo, 16);
        if (tx == 0) ent[(b * Sc + i0 + ty * 4 + r) * Hc + h] = -e;
    }
}

extern "C" void kernel_launch(void* const* d_in, const int* in_sizes, int n_in,
                              void* d_out, int out_size) {
    (void)in_sizes; (void)n_in; (void)out_size;
    const float* x    = (const float*)d_in[0];
    const float* cosb = (const float*)d_in[1];
    const float* sinb = (const float*)d_in[2];
    const float* wq   = (const float*)d_in[3];
    const float* wk   = (const float*)d_in[4];
    const float* wv   = (const float*)d_in[5];
    const float* wo   = (const float*)d_in[6];

    float* out  = (float*)d_out;                       // (B,S,D)
    float* attn = out + (size_t)Mc * Dc;               // (B,S,H,S)
    float* ent  = attn + (size_t)Mc * Hc * (size_t)Sc; // (B,S,H)

    float *q, *k, *v, *ao;
    cudaGetSymbolAddress((void**)&q,  g_q);
    cudaGetSymbolAddress((void**)&k,  g_k);
    cudaGetSymbolAddress((void**)&v,  g_v);
    cudaGetSymbolAddress((void**)&ao, g_ao);

    dim3 gproj(Dc / 128, Mc / 128);
    sgemm_nt<<<gproj, 256>>>(x, wq, q, Mc, Dc, Dc);
    sgemm_nt<<<gproj, 256>>>(x, wk, k, Mc, Dc, Dc);
    sgemm_nt<<<gproj, 256>>>(x, wv, v, Mc, Dc, Dc);
    rope_kernel<<<dim3((Bc * Sc * Hc * 32) / 256, 2), 256>>>(cosb, sinb);
    attn_scores<<<dim3(Sc / 64, Bc * Hc), 256>>>(attn);
    attn_av<<<dim3(Sc / 64, Bc * Hc), 256>>>(attn, ent);
    sgemm_nt<<<gproj, 256>>>(ao, wo, out, Mc, Dc, Dc);
}